// round 12
// baseline (speedup 1.0000x reference)
#include <cuda_runtime.h>
#include <cuda_fp16.h>
#include <stdint.h>

#define B_    8
#define NV_   128
#define NQ_   512
#define DIN   128
#define DPROJ 512
#define HD    256

#define PR_S  136
#define VW_S  264
#define SC_S  132
#define EB_S  136
#define VT_S  136
#define QS_S  264

// ---- device scratch (allocations forbidden) ----
__device__ __half g_vw16[B_*NV_*DPROJ];   // v_*wa : [b*128+i][512]
__device__ __half g_vT16[B_*DPROJ*NV_];   // v_^T  : [b][512][128]
__device__ __half g_WqT [DPROJ*DIN];      // Wq^T f16 [512][128]

__device__ __forceinline__ void mma16816(float* c, const uint32_t* a, const uint32_t* b) {
    asm volatile(
        "mma.sync.aligned.m16n8k16.row.col.f32.f16.f16.f32 "
        "{%0,%1,%2,%3}, {%4,%5,%6,%7}, {%8,%9}, {%0,%1,%2,%3};\n"
        : "+f"(c[0]), "+f"(c[1]), "+f"(c[2]), "+f"(c[3])
        : "r"(a[0]), "r"(a[1]), "r"(a[2]), "r"(a[3]), "r"(b[0]), "r"(b[1]));
}

// ============================================================
// prep: 48 CTAs, 512 thr.  (unchanged from R11 - proven)
//   bid < 32 : v-projection (Wv transposed INLINE into smem Bs)
//   bid >= 32: Wq transpose tile (32 cols) -> g_WqT ; bid==32 zeroes out
// ============================================================
__global__ __launch_bounds__(512) void prep_k(
    const float* __restrict__ v,  const float* __restrict__ Wv,
    const float* __restrict__ Wq, const float* __restrict__ bv,
    const float* __restrict__ wa, float* __restrict__ out)
{
    extern __shared__ __align__(16) char smem[];
    int t = threadIdx.x;
    int bid = blockIdx.x;

    if (bid >= 32) {
        __half* s = (__half*)smem;                 // [32][136]
        int n0 = (bid - 32) * 32;
        if (bid == 32) {
            #pragma unroll
            for (int it = 0; it < 4; it++) out[t + it*512] = 0.f;
        }
        #pragma unroll
        for (int it = 0; it < 8; it++) {
            int fi = t + it*512;
            int k = fi >> 5, nn = fi & 31;
            s[nn*136 + k] = __float2half(Wq[(size_t)k*DPROJ + n0 + nn]);
        }
        __syncthreads();
        {
            int n = t >> 4, kq = (t & 15)*8;
            *(float4*)(g_WqT + (size_t)(n0 + n)*DIN + kq) = *(const float4*)(s + n*136 + kq);
        }
        return;
    }

    __half* As = (__half*)smem;                    // [128][136]
    __half* Bs = (__half*)(smem + 128*PR_S*2);     // [128][136]

    int bn = (bid & 3) * 128;
    int my = bid >> 2;
    int bm = my * 128;

    #pragma unroll
    for (int it = 0; it < 8; it++) {
        int fi = t + it*512;
        int m = fi >> 5, k = (fi & 31)*4;
        float4 f = *(const float4*)(v + (size_t)(bm+m)*DIN + k);
        __half2 h0 = __floats2half2_rn(f.x, f.y);
        __half2 h1 = __floats2half2_rn(f.z, f.w);
        uint2 u; u.x = *(uint32_t*)&h0; u.y = *(uint32_t*)&h1;
        *(uint2*)(As + m*PR_S + k) = u;
    }
    #pragma unroll
    for (int it = 0; it < 32; it++) {
        int fi = t + it*512;
        int k = fi >> 7, n = fi & 127;
        Bs[n*PR_S + k] = __float2half(Wv[(size_t)k*DPROJ + bn + n]);
    }
    __syncthreads();

    int lane = t & 31, wid = t >> 5;
    int warpM = wid >> 2, warpN = wid & 3;
    int lr = lane >> 2, lc = (lane & 3)*2;

    float acc[2][4][4] = {};
    #pragma unroll
    for (int ks = 0; ks < 8; ks++) {
        int k0 = ks*16;
        uint32_t a[2][4], b[4][2];
        #pragma unroll
        for (int mt = 0; mt < 2; mt++) {
            const __half* ab = As + (warpM*32 + mt*16 + lr)*PR_S + k0 + lc;
            a[mt][0] = *(const uint32_t*)ab;
            a[mt][1] = *(const uint32_t*)(ab + 8*PR_S);
            a[mt][2] = *(const uint32_t*)(ab + 8);
            a[mt][3] = *(const uint32_t*)(ab + 8*PR_S + 8);
        }
        #pragma unroll
        for (int nt = 0; nt < 4; nt++) {
            const __half* bb = Bs + (warpN*32 + nt*8 + lr)*PR_S + k0 + lc;
            b[nt][0] = *(const uint32_t*)bb;
            b[nt][1] = *(const uint32_t*)(bb + 8);
        }
        #pragma unroll
        for (int mt = 0; mt < 2; mt++)
            #pragma unroll
            for (int nt = 0; nt < 4; nt++)
                mma16816(acc[mt][nt], a[mt], b[nt]);
    }
    __syncthreads();

    #pragma unroll
    for (int mt = 0; mt < 2; mt++) {
        int rowL = warpM*32 + mt*16 + lr;
        #pragma unroll
        for (int nt = 0; nt < 4; nt++) {
            int colL = warpN*32 + nt*8 + lc;
            int col = bn + colL;
            float b0 = bv[col], b1 = bv[col+1];
            float v00 = acc[mt][nt][0] + b0, v01 = acc[mt][nt][1] + b1;
            float v10 = acc[mt][nt][2] + b0, v11 = acc[mt][nt][3] + b1;
            int row = bm + rowL;
            float w0 = wa[col & 255], w1 = wa[(col+1) & 255];
            *(__half2*)(g_vw16 + (size_t)row*DPROJ + col) =
                __floats2half2_rn(v00*w0, v01*w1);
            *(__half2*)(g_vw16 + (size_t)(row+8)*DPROJ + col) =
                __floats2half2_rn(v10*w0, v11*w1);
            __half* tr = As;
            tr[colL*PR_S + rowL]       = __float2half(v00);
            tr[(colL+1)*PR_S + rowL]   = __float2half(v01);
            tr[colL*PR_S + rowL+8]     = __float2half(v10);
            tr[(colL+1)*PR_S + rowL+8] = __float2half(v11);
        }
    }
    __syncthreads();
    const __half* tr = As;
    #pragma unroll
    for (int it = 0; it < 4; it++) {
        int fi = t + it*512;
        int n = fi >> 4, k = (fi & 15)*8;
        *(float4*)(g_vT16 + ((size_t)my*DPROJ + bn + n)*NV_ + k) =
            *(const float4*)(tr + n*PR_S + k);
    }
}

// ============================================================
// Score kernel, 32-j tiles: 256 CTAs (16 jt x 2 h x 8 b), 512 thr,
// __launch_bounds__(512,2) + 112.3KB smem -> 2 CTAs/SM.
//  P0: qs[32j][256d] = q @ WqT_h + bq
//  P1: S[128i,32j] = vw @ qs^T -> softmax over i -> att
//  P2: T[32j,256d] = e @ vT^T -> ph[256] -> out += ph @ Wo_h
// ============================================================
__global__ __launch_bounds__(512, 2) void score_k(
    const float* __restrict__ q,  const float* __restrict__ bq,
    const float* __restrict__ Wo, const float* __restrict__ bo,
    float* __restrict__ out)
{
    extern __shared__ __align__(16) char smem[];
    __half* X   = (__half*)smem;                  // WqT [256][136] / vw [128][264] / vT [256][136]
    __half* qs  = (__half*)(smem + 69632);        // [32][264]
    float*  sc  = (float*) (smem + 86528);        // [32][132] ; later ph[256]
    __half* ebf = (__half*)(smem + 103424);       // q-in [32][136] / exp [32][136]
    float*  inv = (float*) (smem + 112128);       // [32]

    int t = threadIdx.x;
    int bid = blockIdx.x;
    int jt = bid & 15, h = (bid >> 4) & 1, b = bid >> 5;
    int lane = t & 31, wid = t >> 5;
    int lr = lane >> 2, lc = (lane & 3)*2;
    float* att_out = out + B_*HD;

    // -------- P0: q projection (32 rows) --------
    {
        __half* qin = ebf;   // [32][136]
        #pragma unroll
        for (int it = 0; it < 2; it++) {
            int fi = t + it*512;                 // 1024 float4
            int m = fi >> 5, k = (fi & 31)*4;
            float4 f = *(const float4*)(q + (size_t)(b*NQ_ + jt*32 + m)*DIN + k);
            __half2 h0 = __floats2half2_rn(f.x, f.y);
            __half2 h1 = __floats2half2_rn(f.z, f.w);
            uint2 u; u.x = *(uint32_t*)&h0; u.y = *(uint32_t*)&h1;
            *(uint2*)(qin + m*PR_S + k) = u;
        }
        const __half* wqt = g_WqT + (size_t)(h*HD)*DIN;
        #pragma unroll
        for (int it = 0; it < 8; it++) {
            int fi = t + it*512;                 // 4096 float4
            int n = fi >> 4, k = (fi & 15)*8;
            *(float4*)(X + n*PR_S + k) = *(const float4*)(wqt + (size_t)n*DIN + k);
        }
        __syncthreads();

        int jw0 = (wid >> 3)*16, dw0 = (wid & 7)*32;
        float acc[4][4] = {};
        #pragma unroll
        for (int ks = 0; ks < 8; ks++) {
            int k0 = ks*16;
            uint32_t a[4], bb2[4][2];
            const __half* ab = qin + (jw0 + lr)*PR_S + k0 + lc;
            a[0] = *(const uint32_t*)ab;
            a[1] = *(const uint32_t*)(ab + 8*PR_S);
            a[2] = *(const uint32_t*)(ab + 8);
            a[3] = *(const uint32_t*)(ab + 8*PR_S + 8);
            #pragma unroll
            for (int nt = 0; nt < 4; nt++) {
                const __half* bb = X + (dw0 + nt*8 + lr)*PR_S + k0 + lc;
                bb2[nt][0] = *(const uint32_t*)bb;
                bb2[nt][1] = *(const uint32_t*)(bb + 8);
            }
            #pragma unroll
            for (int nt = 0; nt < 4; nt++)
                mma16816(acc[nt], a, bb2[nt]);
        }
        __syncthreads();

        int j0 = jw0 + lr;
        #pragma unroll
        for (int nt = 0; nt < 4; nt++) {
            int dl = dw0 + nt*8 + lc;
            int col = h*HD + dl;
            float b0 = bq[col], b1 = bq[col+1];
            *(__half2*)(qs + j0*QS_S + dl) =
                __floats2half2_rn(acc[nt][0] + b0, acc[nt][1] + b1);
            *(__half2*)(qs + (j0+8)*QS_S + dl) =
                __floats2half2_rn(acc[nt][2] + b0, acc[nt][3] + b1);
        }
    }

    // -------- load vw into X --------
    const __half* vwg = g_vw16 + ((size_t)b*NV_)*DPROJ + h*HD;
    #pragma unroll
    for (int it = 0; it < 8; it++) {
        int fi = t + it*512;
        int i = fi >> 5, k = (fi & 31)*8;
        *(float4*)(X + i*VW_S + k) = *(const float4*)(vwg + (size_t)i*DPROJ + k);
    }
    __syncthreads();

    // -------- P1: S[128i,32j], warps 4(i)x4(j), warp tile 32x8 --------
    {
        int iw = (wid >> 2)*32, jw = (wid & 3)*8;
        float acc[2][4] = {};
        #pragma unroll
        for (int ks = 0; ks < 16; ks++) {
            int k0 = ks*16;
            uint32_t a[2][4], bq2[2];
            #pragma unroll
            for (int mi = 0; mi < 2; mi++) {
                const __half* ab = X + (iw + mi*16 + lr)*VW_S + k0 + lc;
                a[mi][0] = *(const uint32_t*)ab;
                a[mi][1] = *(const uint32_t*)(ab + 8*VW_S);
                a[mi][2] = *(const uint32_t*)(ab + 8);
                a[mi][3] = *(const uint32_t*)(ab + 8*VW_S + 8);
            }
            const __half* bb = qs + (jw + lr)*QS_S + k0 + lc;
            bq2[0] = *(const uint32_t*)bb;
            bq2[1] = *(const uint32_t*)(bb + 8);
            #pragma unroll
            for (int mi = 0; mi < 2; mi++)
                mma16816(acc[mi], a[mi], bq2);
        }
        #pragma unroll
        for (int mi = 0; mi < 2; mi++) {
            int i0 = iw + mi*16 + lr;
            int j0 = jw + lc;
            sc[j0*SC_S + i0]       = acc[mi][0];
            sc[(j0+1)*SC_S + i0]   = acc[mi][1];
            sc[j0*SC_S + i0+8]     = acc[mi][2];
            sc[(j0+1)*SC_S + i0+8] = acc[mi][3];
        }
    }
    __syncthreads();

    // -------- softmax over i : 16 warps x 2 cols --------
    #pragma unroll
    for (int rr = 0; rr < 2; rr++) {
        int j = wid*2 + rr;
        float4 x = *(float4*)(sc + j*SC_S + lane*4);
        float mx = fmaxf(fmaxf(x.x, x.y), fmaxf(x.z, x.w));
        #pragma unroll
        for (int off = 16; off; off >>= 1)
            mx = fmaxf(mx, __shfl_xor_sync(0xffffffffu, mx, off));
        float4 e;
        e.x = __expf(x.x - mx); e.y = __expf(x.y - mx);
        e.z = __expf(x.z - mx); e.w = __expf(x.w - mx);
        float s = e.x + e.y + e.z + e.w;
        #pragma unroll
        for (int off = 16; off; off >>= 1)
            s += __shfl_xor_sync(0xffffffffu, s, off);
        *(float4*)(sc + j*SC_S + lane*4) = e;
        *(__half2*)(ebf + j*EB_S + lane*4)     = __floats2half2_rn(e.x, e.y);
        *(__half2*)(ebf + j*EB_S + lane*4 + 2) = __floats2half2_rn(e.z, e.w);
        if (lane == 0) inv[j] = 1.0f / s;
    }
    __syncthreads();

    // -------- load vT into X + write att --------
    const __half* vtg = g_vT16 + ((size_t)b*DPROJ + h*HD)*NV_;
    #pragma unroll
    for (int it = 0; it < 8; it++) {
        int fi = t + it*512;
        int d = fi >> 4, k = (fi & 15)*8;
        *(float4*)(X + d*VT_S + k) = *(const float4*)(vtg + (size_t)d*NV_ + k);
    }
    float* attp = att_out + ((size_t)(b*2 + h)*NV_)*NQ_ + jt*32;
    #pragma unroll
    for (int it = 0; it < 8; it++) {
        int e = it*512 + t;
        int i = e >> 5, j = e & 31;
        attp[(size_t)i*NQ_ + j] = sc[j*SC_S + i] * inv[j];
    }
    __syncthreads();

    float* ph = sc;
    if (t < 256) ph[t] = 0.f;
    __syncthreads();

    // -------- P2: warps 2(j:16)x8(d:32); ph smem atomics --------
    {
        int jw2 = (wid >> 3)*16, dw = (wid & 7)*32;
        float acc[4][4] = {};
        #pragma unroll
        for (int ks = 0; ks < 8; ks++) {
            int k0 = ks*16;
            uint32_t a[4], bvv[4][2];
            const __half* ab = ebf + (jw2 + lr)*EB_S + k0 + lc;
            a[0] = *(const uint32_t*)ab;
            a[1] = *(const uint32_t*)(ab + 8*EB_S);
            a[2] = *(const uint32_t*)(ab + 8);
            a[3] = *(const uint32_t*)(ab + 8*EB_S + 8);
            #pragma unroll
            for (int nt = 0; nt < 4; nt++) {
                const __half* bb = X + (dw + nt*8 + lr)*VT_S + k0 + lc;
                bvv[nt][0] = *(const uint32_t*)bb;
                bvv[nt][1] = *(const uint32_t*)(bb + 8);
            }
            #pragma unroll
            for (int nt = 0; nt < 4; nt++)
                mma16816(acc[nt], a, bvv[nt]);
        }
        int j0 = jw2 + lr, j1 = j0 + 8;
        float w0 = inv[j0], w1 = inv[j1];
        #pragma unroll
        for (int nt = 0; nt < 4; nt++) {
            int d0 = dw + nt*8 + lc;
            float q00 = __half2float(qs[j0*QS_S + d0]);
            float q01 = __half2float(qs[j0*QS_S + d0+1]);
            float q10 = __half2float(qs[j1*QS_S + d0]);
            float q11 = __half2float(qs[j1*QS_S + d0+1]);
            float va = acc[nt][0]*w0*q00 + acc[nt][2]*w1*q10;
            float vb = acc[nt][1]*w0*q01 + acc[nt][3]*w1*q11;
            va += __shfl_xor_sync(0xffffffffu, va, 4);
            va += __shfl_xor_sync(0xffffffffu, va, 8);
            va += __shfl_xor_sync(0xffffffffu, va, 16);
            vb += __shfl_xor_sync(0xffffffffu, vb, 4);
            vb += __shfl_xor_sync(0xffffffffu, vb, 8);
            vb += __shfl_xor_sync(0xffffffffu, vb, 16);
            if (lr == 0) {
                atomicAdd(ph + d0,     va);
                atomicAdd(ph + d0 + 1, vb);
            }
        }
    }
    __syncthreads();

    // -------- fused tail: out[b,:] += ph @ Wo[h*256:,:] (+ bo once) --------
    {
        int wd = wid >> 3;
        int wn = wid & 7;
        int n = wn*32 + lane;
        const float* wop = Wo + ((size_t)(h*HD + wd*128))*HD + n;
        const float* php = ph + wd*128;
        float f0 = 0.f, f1 = 0.f, f2 = 0.f, f3 = 0.f;
        #pragma unroll
        for (int d = 0; d < 128; d += 4) {
            f0 += php[d]   * wop[(size_t)(d  )*HD];
            f1 += php[d+1] * wop[(size_t)(d+1)*HD];
            f2 += php[d+2] * wop[(size_t)(d+2)*HD];
            f3 += php[d+3] * wop[(size_t)(d+3)*HD];
        }
        float f = (f0 + f1) + (f2 + f3);
        if (wd == 0 && (bid & 31) == 0) f += bo[n];
        atomicAdd(&out[b*HD + n], f);
    }
}

// ============================================================
extern "C" void kernel_launch(void* const* d_in, const int* in_sizes, int n_in,
                              void* d_out, int out_size)
{
    const float* v  = (const float*)d_in[0];
    const float* q  = (const float*)d_in[1];
    const float* Wv = (const float*)d_in[2];
    const float* bv = (const float*)d_in[3];
    const float* Wq = (const float*)d_in[4];
    const float* bq = (const float*)d_in[5];
    const float* wa = (const float*)d_in[6];
    // d_in[7] = ba : constant shift before softmax -> drops out
    const float* Wo = (const float*)d_in[8];
    const float* bo = (const float*)d_in[9];
    float* out = (float*)d_out;

    const int PSM = 2 * 128 * PR_S * 2;   // 69632 B
    const int SSM = 112256;               // 2 CTAs/SM
    cudaFuncSetAttribute(prep_k,  cudaFuncAttributeMaxDynamicSharedMemorySize, PSM);
    cudaFuncSetAttribute(score_k, cudaFuncAttributeMaxDynamicSharedMemorySize, SSM);

    prep_k<<<48, 512, PSM>>>(v, Wv, Wq, bv, wa, out);
    score_k<<<256, 512, SSM>>>(q, bq, Wo, bo, out);
}

// round 13
// speedup vs baseline: 1.2554x; 1.2554x over previous
#include <cuda_runtime.h>
#include <cuda_fp16.h>
#include <stdint.h>

#define B_    8
#define NV_   128
#define NQ_   512
#define DIN   128
#define DPROJ 512
#define HD    256

#define PR_S  136
#define VW_S  264
#define SC_S  132
#define EB_S  136
#define VT_S  136
#define QS_S  264

// ---- device scratch (allocations forbidden) ----
__device__ __half g_vw16[B_*NV_*DPROJ];   // v_*wa : [b*128+i][512]
__device__ __half g_vT16[B_*DPROJ*NV_];   // v_^T  : [b][512][128]
__device__ __half g_WqT [DPROJ*DIN];      // Wq^T f16 [512][128]

__device__ __forceinline__ void mma16816(float* c, const uint32_t* a, const uint32_t* b) {
    asm volatile(
        "mma.sync.aligned.m16n8k16.row.col.f32.f16.f16.f32 "
        "{%0,%1,%2,%3}, {%4,%5,%6,%7}, {%8,%9}, {%0,%1,%2,%3};\n"
        : "+f"(c[0]), "+f"(c[1]), "+f"(c[2]), "+f"(c[3])
        : "r"(a[0]), "r"(a[1]), "r"(a[2]), "r"(a[3]), "r"(b[0]), "r"(b[1]));
}

__device__ __forceinline__ void cp_async16(void* s, const void* g) {
    uint32_t sa = (uint32_t)__cvta_generic_to_shared(s);
    asm volatile("cp.async.cg.shared.global [%0], [%1], 16;" :: "r"(sa), "l"(g));
}
#define CP_COMMIT()  asm volatile("cp.async.commit_group;" ::: "memory")
#define CP_WAIT(n)   asm volatile("cp.async.wait_group %0;" :: "n"(n) : "memory")

// ============================================================
// prep: 48 CTAs, 512 thr.  (unchanged from R11 - proven)
// ============================================================
__global__ __launch_bounds__(512) void prep_k(
    const float* __restrict__ v,  const float* __restrict__ Wv,
    const float* __restrict__ Wq, const float* __restrict__ bv,
    const float* __restrict__ wa, float* __restrict__ out)
{
    extern __shared__ __align__(16) char smem[];
    int t = threadIdx.x;
    int bid = blockIdx.x;

    if (bid >= 32) {
        __half* s = (__half*)smem;                 // [32][136]
        int n0 = (bid - 32) * 32;
        if (bid == 32) {
            #pragma unroll
            for (int it = 0; it < 4; it++) out[t + it*512] = 0.f;
        }
        #pragma unroll
        for (int it = 0; it < 8; it++) {
            int fi = t + it*512;
            int k = fi >> 5, nn = fi & 31;
            s[nn*136 + k] = __float2half(Wq[(size_t)k*DPROJ + n0 + nn]);
        }
        __syncthreads();
        {
            int n = t >> 4, kq = (t & 15)*8;
            *(float4*)(g_WqT + (size_t)(n0 + n)*DIN + kq) = *(const float4*)(s + n*136 + kq);
        }
        return;
    }

    __half* As = (__half*)smem;                    // [128][136]
    __half* Bs = (__half*)(smem + 128*PR_S*2);     // [128][136]

    int bn = (bid & 3) * 128;
    int my = bid >> 2;
    int bm = my * 128;

    #pragma unroll
    for (int it = 0; it < 8; it++) {
        int fi = t + it*512;
        int m = fi >> 5, k = (fi & 31)*4;
        float4 f = *(const float4*)(v + (size_t)(bm+m)*DIN + k);
        __half2 h0 = __floats2half2_rn(f.x, f.y);
        __half2 h1 = __floats2half2_rn(f.z, f.w);
        uint2 u; u.x = *(uint32_t*)&h0; u.y = *(uint32_t*)&h1;
        *(uint2*)(As + m*PR_S + k) = u;
    }
    #pragma unroll
    for (int it = 0; it < 32; it++) {
        int fi = t + it*512;
        int k = fi >> 7, n = fi & 127;
        Bs[n*PR_S + k] = __float2half(Wv[(size_t)k*DPROJ + bn + n]);
    }
    __syncthreads();

    int lane = t & 31, wid = t >> 5;
    int warpM = wid >> 2, warpN = wid & 3;
    int lr = lane >> 2, lc = (lane & 3)*2;

    float acc[2][4][4] = {};
    #pragma unroll
    for (int ks = 0; ks < 8; ks++) {
        int k0 = ks*16;
        uint32_t a[2][4], b[4][2];
        #pragma unroll
        for (int mt = 0; mt < 2; mt++) {
            const __half* ab = As + (warpM*32 + mt*16 + lr)*PR_S + k0 + lc;
            a[mt][0] = *(const uint32_t*)ab;
            a[mt][1] = *(const uint32_t*)(ab + 8*PR_S);
            a[mt][2] = *(const uint32_t*)(ab + 8);
            a[mt][3] = *(const uint32_t*)(ab + 8*PR_S + 8);
        }
        #pragma unroll
        for (int nt = 0; nt < 4; nt++) {
            const __half* bb = Bs + (warpN*32 + nt*8 + lr)*PR_S + k0 + lc;
            b[nt][0] = *(const uint32_t*)bb;
            b[nt][1] = *(const uint32_t*)(bb + 8);
        }
        #pragma unroll
        for (int mt = 0; mt < 2; mt++)
            #pragma unroll
            for (int nt = 0; nt < 4; nt++)
                mma16816(acc[mt][nt], a[mt], b[nt]);
    }
    __syncthreads();

    #pragma unroll
    for (int mt = 0; mt < 2; mt++) {
        int rowL = warpM*32 + mt*16 + lr;
        #pragma unroll
        for (int nt = 0; nt < 4; nt++) {
            int colL = warpN*32 + nt*8 + lc;
            int col = bn + colL;
            float b0 = bv[col], b1 = bv[col+1];
            float v00 = acc[mt][nt][0] + b0, v01 = acc[mt][nt][1] + b1;
            float v10 = acc[mt][nt][2] + b0, v11 = acc[mt][nt][3] + b1;
            int row = bm + rowL;
            float w0 = wa[col & 255], w1 = wa[(col+1) & 255];
            *(__half2*)(g_vw16 + (size_t)row*DPROJ + col) =
                __floats2half2_rn(v00*w0, v01*w1);
            *(__half2*)(g_vw16 + (size_t)(row+8)*DPROJ + col) =
                __floats2half2_rn(v10*w0, v11*w1);
            __half* tr = As;
            tr[colL*PR_S + rowL]       = __float2half(v00);
            tr[(colL+1)*PR_S + rowL]   = __float2half(v01);
            tr[colL*PR_S + rowL+8]     = __float2half(v10);
            tr[(colL+1)*PR_S + rowL+8] = __float2half(v11);
        }
    }
    __syncthreads();
    const __half* tr = As;
    #pragma unroll
    for (int it = 0; it < 4; it++) {
        int fi = t + it*512;
        int n = fi >> 4, k = (fi & 15)*8;
        *(float4*)(g_vT16 + ((size_t)my*DPROJ + bn + n)*NV_ + k) =
            *(const float4*)(tr + n*PR_S + k);
    }
}

// ============================================================
// Score kernel (R11 64-j tiles) + cp.async prefetch pipelining.
// smem: X(WqT/vT) | VW(own region) | qs | sc | ebf | inv  = 222.5KB
//  groups: A=WqT, B=vw (issued at start), C=vT (issued after P0)
// ============================================================
__global__ __launch_bounds__(512) void score_k(
    const float* __restrict__ q,  const float* __restrict__ bq,
    const float* __restrict__ Wo, const float* __restrict__ bo,
    float* __restrict__ out)
{
    extern __shared__ __align__(16) char smem[];
    __half* X   = (__half*)smem;                  // WqT [256][136] -> vT [256][136]
    __half* VW  = (__half*)(smem + 69632);        // vw [128][264]
    __half* qs  = (__half*)(smem + 137216);       // [64][264]
    float*  sc  = (float*) (smem + 171008);       // [64][132] ; later ph[256]
    __half* ebf = (__half*)(smem + 204800);       // q-in [64][136] / exp [64][136]
    float*  inv = (float*) (smem + 222208);       // [64]

    int t = threadIdx.x;
    int bid = blockIdx.x;
    int jt = bid & 7, h = (bid >> 3) & 1, b = bid >> 4;
    int lane = t & 31, wid = t >> 5;
    int lr = lane >> 2, lc = (lane & 3)*2;
    float* att_out = out + B_*HD;

    // ---- issue async loads: WqT (group A), vw (group B) ----
    {
        const __half* wqt = g_WqT + (size_t)(h*HD)*DIN;
        #pragma unroll
        for (int it = 0; it < 8; it++) {
            int fi = t + it*512;                 // 4096 x16B
            int n = fi >> 4, k = (fi & 15)*8;
            cp_async16(X + n*PR_S + k, wqt + (size_t)n*DIN + k);
        }
        CP_COMMIT();   // group A
        const __half* vwg = g_vw16 + ((size_t)b*NV_)*DPROJ + h*HD;
        #pragma unroll
        for (int it = 0; it < 8; it++) {
            int fi = t + it*512;                 // 4096 x16B
            int i = fi >> 5, k = (fi & 31)*8;
            cp_async16(VW + i*VW_S + k, vwg + (size_t)i*DPROJ + k);
        }
        CP_COMMIT();   // group B
    }

    // ---- regular load + convert q-in (needs f32->f16) ----
    {
        __half* qin = ebf;
        #pragma unroll
        for (int it = 0; it < 4; it++) {
            int fi = t + it*512;                 // 2048 float4
            int m = fi >> 5, k = (fi & 31)*4;
            float4 f = *(const float4*)(q + (size_t)(b*NQ_ + jt*64 + m)*DIN + k);
            __half2 h0 = __floats2half2_rn(f.x, f.y);
            __half2 h1 = __floats2half2_rn(f.z, f.w);
            uint2 u; u.x = *(uint32_t*)&h0; u.y = *(uint32_t*)&h1;
            *(uint2*)(qin + m*PR_S + k) = u;
        }
    }
    CP_WAIT(1);          // A done (B may be in flight)
    __syncthreads();

    // -------- P0: q projection --------
    {
        __half* qin = ebf;
        int wj = wid >> 3, wd = wid & 7;
        float acc[2][4][4] = {};
        #pragma unroll
        for (int ks = 0; ks < 8; ks++) {
            int k0 = ks*16;
            uint32_t a[2][4], bb2[4][2];
            #pragma unroll
            for (int mt = 0; mt < 2; mt++) {
                const __half* ab = qin + (wj*32 + mt*16 + lr)*PR_S + k0 + lc;
                a[mt][0] = *(const uint32_t*)ab;
                a[mt][1] = *(const uint32_t*)(ab + 8*PR_S);
                a[mt][2] = *(const uint32_t*)(ab + 8);
                a[mt][3] = *(const uint32_t*)(ab + 8*PR_S + 8);
            }
            #pragma unroll
            for (int nt = 0; nt < 4; nt++) {
                const __half* bb = X + (wd*32 + nt*8 + lr)*PR_S + k0 + lc;
                bb2[nt][0] = *(const uint32_t*)bb;
                bb2[nt][1] = *(const uint32_t*)(bb + 8);
            }
            #pragma unroll
            for (int mt = 0; mt < 2; mt++)
                #pragma unroll
                for (int nt = 0; nt < 4; nt++)
                    mma16816(acc[mt][nt], a[mt], bb2[nt]);
        }
        __syncthreads();   // all warps done reading X (WqT) and qin

        // ---- issue vT async into X (group C) — overlaps qs-store, P1, softmax
        {
            const __half* vtg = g_vT16 + ((size_t)b*DPROJ + h*HD)*NV_;
            #pragma unroll
            for (int it = 0; it < 8; it++) {
                int fi = t + it*512;             // 4096 x16B
                int d = fi >> 4, k = (fi & 15)*8;
                cp_async16(X + d*VT_S + k, vtg + (size_t)d*NV_ + k);
            }
            CP_COMMIT();   // group C
        }

        #pragma unroll
        for (int mt = 0; mt < 2; mt++) {
            int j0 = wj*32 + mt*16 + lr;
            #pragma unroll
            for (int nt = 0; nt < 4; nt++) {
                int dl = wd*32 + nt*8 + lc;
                int col = h*HD + dl;
                float b0 = bq[col], b1 = bq[col+1];
                *(__half2*)(qs + j0*QS_S + dl) =
                    __floats2half2_rn(acc[mt][nt][0] + b0, acc[mt][nt][1] + b1);
                *(__half2*)(qs + (j0+8)*QS_S + dl) =
                    __floats2half2_rn(acc[mt][nt][2] + b0, acc[mt][nt][3] + b1);
            }
        }
    }
    CP_WAIT(1);          // B done (vw ready; C may be in flight)
    __syncthreads();

    // -------- P1: score MMA on VW/qs --------
    {
        int iw = (wid >> 2)*32, jw = (wid & 3)*16;
        float acc[2][2][4] = {};
        #pragma unroll
        for (int ks = 0; ks < 16; ks++) {
            int k0 = ks*16;
            uint32_t a[2][4], bq2[2][2];
            #pragma unroll
            for (int mi = 0; mi < 2; mi++) {
                const __half* ab = VW + (iw + mi*16 + lr)*VW_S + k0 + lc;
                a[mi][0] = *(const uint32_t*)ab;
                a[mi][1] = *(const uint32_t*)(ab + 8*VW_S);
                a[mi][2] = *(const uint32_t*)(ab + 8);
                a[mi][3] = *(const uint32_t*)(ab + 8*VW_S + 8);
            }
            #pragma unroll
            for (int nj = 0; nj < 2; nj++) {
                const __half* bb = qs + (jw + nj*8 + lr)*QS_S + k0 + lc;
                bq2[nj][0] = *(const uint32_t*)bb;
                bq2[nj][1] = *(const uint32_t*)(bb + 8);
            }
            #pragma unroll
            for (int mi = 0; mi < 2; mi++)
                #pragma unroll
                for (int nj = 0; nj < 2; nj++)
                    mma16816(acc[mi][nj], a[mi], bq2[nj]);
        }
        #pragma unroll
        for (int mi = 0; mi < 2; mi++) {
            int i0 = iw + mi*16 + lr;
            #pragma unroll
            for (int nj = 0; nj < 2; nj++) {
                int j0 = jw + nj*8 + lc;
                sc[j0*SC_S + i0]       = acc[mi][nj][0];
                sc[(j0+1)*SC_S + i0]   = acc[mi][nj][1];
                sc[j0*SC_S + i0+8]     = acc[mi][nj][2];
                sc[(j0+1)*SC_S + i0+8] = acc[mi][nj][3];
            }
        }
    }
    __syncthreads();

    // -------- softmax over i --------
    #pragma unroll
    for (int rr = 0; rr < 4; rr++) {
        int j = wid*4 + rr;
        float4 x = *(float4*)(sc + j*SC_S + lane*4);
        float mx = fmaxf(fmaxf(x.x, x.y), fmaxf(x.z, x.w));
        #pragma unroll
        for (int off = 16; off; off >>= 1)
            mx = fmaxf(mx, __shfl_xor_sync(0xffffffffu, mx, off));
        float4 e;
        e.x = __expf(x.x - mx); e.y = __expf(x.y - mx);
        e.z = __expf(x.z - mx); e.w = __expf(x.w - mx);
        float s = e.x + e.y + e.z + e.w;
        #pragma unroll
        for (int off = 16; off; off >>= 1)
            s += __shfl_xor_sync(0xffffffffu, s, off);
        *(float4*)(sc + j*SC_S + lane*4) = e;
        *(__half2*)(ebf + j*EB_S + lane*4)     = __floats2half2_rn(e.x, e.y);
        *(__half2*)(ebf + j*EB_S + lane*4 + 2) = __floats2half2_rn(e.z, e.w);
        if (lane == 0) inv[j] = 1.0f / s;
    }
    __syncthreads();

    // -------- write att --------
    float* attp = att_out + ((size_t)(b*2 + h)*NV_)*NQ_ + jt*64;
    #pragma unroll
    for (int it = 0; it < 16; it++) {
        int e = it*512 + t;
        int i = e >> 6, j = e & 63;
        attp[(size_t)i*NQ_ + j] = sc[j*SC_S + i] * inv[j];
    }

    CP_WAIT(0);          // vT ready
    __syncthreads();

    float* ph = sc;
    if (t < 256) ph[t] = 0.f;
    __syncthreads();

    // -------- P2: MMA on ebf/X(vT); ph smem atomics --------
    {
        int jw2 = (wid >> 3)*32, dw = (wid & 7)*32;
        float acc[2][4][4] = {};
        #pragma unroll
        for (int ks = 0; ks < 8; ks++) {
            int k0 = ks*16;
            uint32_t a[2][4], bvv[4][2];
            #pragma unroll
            for (int mi = 0; mi < 2; mi++) {
                const __half* ab = ebf + (jw2 + mi*16 + lr)*EB_S + k0 + lc;
                a[mi][0] = *(const uint32_t*)ab;
                a[mi][1] = *(const uint32_t*)(ab + 8*EB_S);
                a[mi][2] = *(const uint32_t*)(ab + 8);
                a[mi][3] = *(const uint32_t*)(ab + 8*EB_S + 8);
            }
            #pragma unroll
            for (int nt = 0; nt < 4; nt++) {
                const __half* bb = X + (dw + nt*8 + lr)*VT_S + k0 + lc;
                bvv[nt][0] = *(const uint32_t*)bb;
                bvv[nt][1] = *(const uint32_t*)(bb + 8);
            }
            #pragma unroll
            for (int mi = 0; mi < 2; mi++)
                #pragma unroll
                for (int nt = 0; nt < 4; nt++)
                    mma16816(acc[mi][nt], a[mi], bvv[nt]);
        }
        #pragma unroll
        for (int nt = 0; nt < 4; nt++) {
            int d0 = dw + nt*8 + lc;
            float va = 0.f, vb = 0.f;
            #pragma unroll
            for (int mi = 0; mi < 2; mi++) {
                int j0 = jw2 + mi*16 + lr, j1 = j0 + 8;
                float w0 = inv[j0], w1 = inv[j1];
                float q00 = __half2float(qs[j0*QS_S + d0]);
                float q01 = __half2float(qs[j0*QS_S + d0+1]);
                float q10 = __half2float(qs[j1*QS_S + d0]);
                float q11 = __half2float(qs[j1*QS_S + d0+1]);
                va += acc[mi][nt][0]*w0*q00 + acc[mi][nt][2]*w1*q10;
                vb += acc[mi][nt][1]*w0*q01 + acc[mi][nt][3]*w1*q11;
            }
            va += __shfl_xor_sync(0xffffffffu, va, 4);
            va += __shfl_xor_sync(0xffffffffu, va, 8);
            va += __shfl_xor_sync(0xffffffffu, va, 16);
            vb += __shfl_xor_sync(0xffffffffu, vb, 4);
            vb += __shfl_xor_sync(0xffffffffu, vb, 8);
            vb += __shfl_xor_sync(0xffffffffu, vb, 16);
            if (lr == 0) {
                atomicAdd(ph + d0,     va);
                atomicAdd(ph + d0 + 1, vb);
            }
        }
    }
    __syncthreads();

    // -------- fused tail: out[b,:] += ph @ Wo[h*256:,:] (+ bo once) --------
    {
        int wd = wid >> 3;
        int wn = wid & 7;
        int n = wn*32 + lane;
        const float* wop = Wo + ((size_t)(h*HD + wd*128))*HD + n;
        const float* php = ph + wd*128;
        float f0 = 0.f, f1 = 0.f, f2 = 0.f, f3 = 0.f;
        #pragma unroll
        for (int d = 0; d < 128; d += 4) {
            f0 += php[d]   * wop[(size_t)(d  )*HD];
            f1 += php[d+1] * wop[(size_t)(d+1)*HD];
            f2 += php[d+2] * wop[(size_t)(d+2)*HD];
            f3 += php[d+3] * wop[(size_t)(d+3)*HD];
        }
        float f = (f0 + f1) + (f2 + f3);
        if (wd == 0 && (bid & 15) == 0) f += bo[n];
        atomicAdd(&out[b*HD + n], f);
    }
}

// ============================================================
extern "C" void kernel_launch(void* const* d_in, const int* in_sizes, int n_in,
                              void* d_out, int out_size)
{
    const float* v  = (const float*)d_in[0];
    const float* q  = (const float*)d_in[1];
    const float* Wv = (const float*)d_in[2];
    const float* bv = (const float*)d_in[3];
    const float* Wq = (const float*)d_in[4];
    const float* bq = (const float*)d_in[5];
    const float* wa = (const float*)d_in[6];
    // d_in[7] = ba : constant shift before softmax -> drops out
    const float* Wo = (const float*)d_in[8];
    const float* bo = (const float*)d_in[9];
    float* out = (float*)d_out;

    const int PSM = 2 * 128 * PR_S * 2;   // 69632 B
    const int SSM = 222464;               // X + VW + qs + sc + ebf + inv
    cudaFuncSetAttribute(prep_k,  cudaFuncAttributeMaxDynamicSharedMemorySize, PSM);
    cudaFuncSetAttribute(score_k, cudaFuncAttributeMaxDynamicSharedMemorySize, SSM);

    prep_k<<<48, 512, PSM>>>(v, Wv, Wq, bv, wa, out);
    score_k<<<128, 512, SSM>>>(q, bq, Wo, bo, out);
}